// round 12
// baseline (speedup 1.0000x reference)
#include <cuda_runtime.h>
#include <cuda_bf16.h>

// out[n] = dot(inputs[n, 0:272], weights) + bias
// weights[0:16]  = kernel
// weights[16+x]  = k[4a1+a2]*k[4b1+b2]*w1 + k[4a1+b2]*k[4b1+a2]*w2
//
// HBM-bound stream (544 MB read once, ~6.9 TB/s achieved). Two kernels:
//  1) build_weights: one block computes the 272-float weight vector into a
//     __device__ global (runs once, ~2 us).
//  2) main: prologue-free (no smem, no __syncthreads), 64-thread blocks
//     (18 blocks/SM at 56 regs = 36 warps/SM; fine-grained churn keeps the
//     load queue continuously fed). Each warp: 4 rows, 9 front-batched
//     LDG.128 + 3 L1-hot weight loads, merged 9-shuffle butterfly reduce,
//     4-lane coalesced store.

#define UNITS 16
#define D 272            // floats per row
#define D4 68            // float4 per row
#define WARPS_PER_BLOCK 2
#define THREADS (WARPS_PER_BLOCK * 32)
#define ROWS_PER_WARP 4
#define ROWS_PER_BLOCK (WARPS_PER_BLOCK * ROWS_PER_WARP)   // 8

__device__ __align__(16) float g_w[D];
__device__ float g_bias;

__device__ __forceinline__ float4 ldcs4(const float4* p) { return __ldcs(p); }

__global__ void build_weights_kernel(const float* __restrict__ kern,
                                     const float* __restrict__ w1p,
                                     const float* __restrict__ w2p,
                                     const float* __restrict__ biasp)
{
    const int tid = threadIdx.x;
    if (tid < UNITS) g_w[tid] = kern[tid];
    if (tid < 256) {
        const float w1 = *w1p;
        const float w2 = *w2p;
        const int x1 = tid >> 4;
        const int x2 = tid & 15;
        const int a1 = x1 >> 2, b1 = x1 & 3;
        const int a2 = x2 >> 2, b2 = x2 & 3;
        g_w[UNITS + tid] = kern[4 * a1 + a2] * kern[4 * b1 + b2] * w1
                         + kern[4 * a1 + b2] * kern[4 * b1 + a2] * w2;
    }
    if (tid == 0) g_bias = *biasp;
}

__global__ __launch_bounds__(THREADS)
void linear_gemv_kernel(const float* __restrict__ in,
                        float* __restrict__ out,
                        int n)
{
    const int lane = threadIdx.x & 31;
    const int warp = threadIdx.x >> 5;

    const float4* __restrict__ wp  = (const float4*)g_w;
    const float4* __restrict__ in4 = (const float4*)in;

    const long long row0 = ((long long)blockIdx.x * WARPS_PER_BLOCK + warp)
                           * ROWS_PER_WARP;
    if (row0 >= n) return;

    if (row0 + ROWS_PER_WARP <= n) {
        const float4* r0 = in4 + row0 * D4;
        const float4* r1 = r0 + D4;
        const float4* r2 = r1 + D4;
        const float4* r3 = r2 + D4;

        // ---- Front-batch 12 independent loads per lane ----
        float4 a00 = ldcs4(r0 + lane);
        float4 a01 = ldcs4(r0 + lane + 32);
        float4 a10 = ldcs4(r1 + lane);
        float4 a11 = ldcs4(r1 + lane + 32);
        float4 a20 = ldcs4(r2 + lane);
        float4 a21 = ldcs4(r2 + lane + 32);
        float4 a30 = ldcs4(r3 + lane);
        float4 a31 = ldcs4(r3 + lane + 32);
        // Tail float4 64..67 for all 4 rows: lane/4 -> row, lane%4 -> col.
        float4 at = make_float4(0.f, 0.f, 0.f, 0.f);
        if (lane < 16)
            at = ldcs4(in4 + (row0 + (lane >> 2)) * D4 + 64 + (lane & 3));

        // Weight loads (L1/L2-hot, independent of row loads).
        const float4 b0 = __ldg(wp + lane);
        const float4 b1 = __ldg(wp + lane + 32);
        float4 bt = make_float4(0.f, 0.f, 0.f, 0.f);
        if (lane < 16) bt = __ldg(wp + 64 + (lane & 3));

        // ---- FMA reduction ----
        float s0 = 0.f, s1 = 0.f, s2 = 0.f, s3 = 0.f;
        s0 = fmaf(a00.x, b0.x, s0); s0 = fmaf(a00.y, b0.y, s0);
        s0 = fmaf(a00.z, b0.z, s0); s0 = fmaf(a00.w, b0.w, s0);
        s0 = fmaf(a01.x, b1.x, s0); s0 = fmaf(a01.y, b1.y, s0);
        s0 = fmaf(a01.z, b1.z, s0); s0 = fmaf(a01.w, b1.w, s0);

        s1 = fmaf(a10.x, b0.x, s1); s1 = fmaf(a10.y, b0.y, s1);
        s1 = fmaf(a10.z, b0.z, s1); s1 = fmaf(a10.w, b0.w, s1);
        s1 = fmaf(a11.x, b1.x, s1); s1 = fmaf(a11.y, b1.y, s1);
        s1 = fmaf(a11.z, b1.z, s1); s1 = fmaf(a11.w, b1.w, s1);

        s2 = fmaf(a20.x, b0.x, s2); s2 = fmaf(a20.y, b0.y, s2);
        s2 = fmaf(a20.z, b0.z, s2); s2 = fmaf(a20.w, b0.w, s2);
        s2 = fmaf(a21.x, b1.x, s2); s2 = fmaf(a21.y, b1.y, s2);
        s2 = fmaf(a21.z, b1.z, s2); s2 = fmaf(a21.w, b1.w, s2);

        s3 = fmaf(a30.x, b0.x, s3); s3 = fmaf(a30.y, b0.y, s3);
        s3 = fmaf(a30.z, b0.z, s3); s3 = fmaf(a30.w, b0.w, s3);
        s3 = fmaf(a31.x, b1.x, s3); s3 = fmaf(a31.y, b1.y, s3);
        s3 = fmaf(a31.z, b1.z, s3); s3 = fmaf(a31.w, b1.w, s3);

        // Tail: lane/4 selects destination accumulator.
        const float ts = fmaf(at.x, bt.x,
                         fmaf(at.y, bt.y,
                         fmaf(at.z, bt.z, at.w * bt.w)));
        const int tr = lane >> 2;
        if (lane < 16) {
            if      (tr == 0) s0 += ts;
            else if (tr == 1) s1 += ts;
            else if (tr == 2) s2 += ts;
            else              s3 += ts;
        }

        // ---- Merged butterfly reduce: 9 shuffles total ----
        float x01 = (lane & 1) ? s1 : s0;
        float y01 = (lane & 1) ? s0 : s1;
        x01 += __shfl_xor_sync(0xFFFFFFFFu, y01, 1);
        float x23 = (lane & 1) ? s3 : s2;
        float y23 = (lane & 1) ? s2 : s3;
        x23 += __shfl_xor_sync(0xFFFFFFFFu, y23, 1);
        float x = (lane & 2) ? x23 : x01;
        float y = (lane & 2) ? x01 : x23;
        x += __shfl_xor_sync(0xFFFFFFFFu, y, 2);
        x += __shfl_xor_sync(0xFFFFFFFFu, x, 4);
        x += __shfl_xor_sync(0xFFFFFFFFu, x, 8);
        x += __shfl_xor_sync(0xFFFFFFFFu, x, 16);

        // Lane j (j<4) holds total for row0+j. 16B coalesced store.
        if (lane < 4) out[row0 + lane] = x + g_bias;
    } else {
        // Remainder rows (n not multiple of 4): one row at a time, warp-wide.
        const float4 b0 = __ldg(wp + lane);
        const float4 b1 = __ldg(wp + lane + 32);
        for (long long r = row0; r < n; ++r) {
            const float4* rp = in4 + r * D4;
            float s = 0.f;
            float4 a = ldcs4(rp + lane);
            s = fmaf(a.x, b0.x, s); s = fmaf(a.y, b0.y, s);
            s = fmaf(a.z, b0.z, s); s = fmaf(a.w, b0.w, s);
            a = ldcs4(rp + lane + 32);
            s = fmaf(a.x, b1.x, s); s = fmaf(a.y, b1.y, s);
            s = fmaf(a.z, b1.z, s); s = fmaf(a.w, b1.w, s);
            if (lane < 4) {
                float4 t = ldcs4(rp + 64 + lane);
                float4 bw = __ldg(wp + 64 + lane);
                s = fmaf(t.x, bw.x, s); s = fmaf(t.y, bw.y, s);
                s = fmaf(t.z, bw.z, s); s = fmaf(t.w, bw.w, s);
            }
            #pragma unroll
            for (int off = 16; off > 0; off >>= 1)
                s += __shfl_xor_sync(0xFFFFFFFFu, s, off);
            if (lane == 0) out[r] = s + g_bias;
        }
    }
}

extern "C" void kernel_launch(void* const* d_in, const int* in_sizes, int n_in,
                              void* d_out, int out_size)
{
    const float* in   = (const float*)d_in[0];   // [N, 272]
    const float* kern = (const float*)d_in[1];   // [16]
    const float* w1   = (const float*)d_in[2];   // [1]
    const float* w2   = (const float*)d_in[3];   // [1]
    const float* bias = (const float*)d_in[4];   // [1]
    float* out = (float*)d_out;

    const int n = out_size;  // 500000 rows
    const int blocks = (n + ROWS_PER_BLOCK - 1) / ROWS_PER_BLOCK;

    build_weights_kernel<<<1, 256>>>(kern, w1, w2, bias);
    linear_gemv_kernel<<<blocks, THREADS>>>(in, out, n);
}

// round 14
// speedup vs baseline: 1.0517x; 1.0517x over previous
#include <cuda_runtime.h>
#include <cuda_bf16.h>

// out[n] = dot(inputs[n, 0:272], weights) + bias
// weights[0:16]  = kernel
// weights[16+x]  = k[4a1+a2]*k[4b1+b2]*w1 + k[4a1+b2]*k[4b1+a2]*w2
//
// HBM-bound stream (544 MB read once, ~6.9 TB/s achieved). Two kernels:
//  1) build_weights: one block computes the 272-float weight vector into a
//     __device__ global (runs once, ~2 us).
//  2) main: prologue-free (no smem, no __syncthreads), 64-thread blocks
//     (18 blocks/SM at 56 regs = 36 warps/SM; fine-grained churn keeps the
//     load queue continuously fed). Each warp: 4 rows, 9 front-batched
//     LDG.128 + 3 L1-hot weight loads, merged 9-shuffle butterfly reduce,
//     4-lane coalesced store.

#define UNITS 16
#define D 272            // floats per row
#define D4 68            // float4 per row
#define WARPS_PER_BLOCK 2
#define THREADS (WARPS_PER_BLOCK * 32)
#define ROWS_PER_WARP 4
#define ROWS_PER_BLOCK (WARPS_PER_BLOCK * ROWS_PER_WARP)   // 8

__device__ __align__(16) float g_w[D];
__device__ float g_bias;

__device__ __forceinline__ float4 ldcs4(const float4* p) { return __ldcs(p); }

__global__ void build_weights_kernel(const float* __restrict__ kern,
                                     const float* __restrict__ w1p,
                                     const float* __restrict__ w2p,
                                     const float* __restrict__ biasp)
{
    const int tid = threadIdx.x;
    if (tid < UNITS) g_w[tid] = kern[tid];
    if (tid < 256) {
        const float w1 = *w1p;
        const float w2 = *w2p;
        const int x1 = tid >> 4;
        const int x2 = tid & 15;
        const int a1 = x1 >> 2, b1 = x1 & 3;
        const int a2 = x2 >> 2, b2 = x2 & 3;
        g_w[UNITS + tid] = kern[4 * a1 + a2] * kern[4 * b1 + b2] * w1
                         + kern[4 * a1 + b2] * kern[4 * b1 + a2] * w2;
    }
    if (tid == 0) g_bias = *biasp;
}

__global__ __launch_bounds__(THREADS)
void linear_gemv_kernel(const float* __restrict__ in,
                        float* __restrict__ out,
                        int n)
{
    const int lane = threadIdx.x & 31;
    const int warp = threadIdx.x >> 5;

    const float4* __restrict__ wp  = (const float4*)g_w;
    const float4* __restrict__ in4 = (const float4*)in;

    const long long row0 = ((long long)blockIdx.x * WARPS_PER_BLOCK + warp)
                           * ROWS_PER_WARP;
    if (row0 >= n) return;

    if (row0 + ROWS_PER_WARP <= n) {
        const float4* r0 = in4 + row0 * D4;
        const float4* r1 = r0 + D4;
        const float4* r2 = r1 + D4;
        const float4* r3 = r2 + D4;

        // ---- Front-batch 12 independent loads per lane ----
        float4 a00 = ldcs4(r0 + lane);
        float4 a01 = ldcs4(r0 + lane + 32);
        float4 a10 = ldcs4(r1 + lane);
        float4 a11 = ldcs4(r1 + lane + 32);
        float4 a20 = ldcs4(r2 + lane);
        float4 a21 = ldcs4(r2 + lane + 32);
        float4 a30 = ldcs4(r3 + lane);
        float4 a31 = ldcs4(r3 + lane + 32);
        // Tail float4 64..67 for all 4 rows: lane/4 -> row, lane%4 -> col.
        float4 at = make_float4(0.f, 0.f, 0.f, 0.f);
        if (lane < 16)
            at = ldcs4(in4 + (row0 + (lane >> 2)) * D4 + 64 + (lane & 3));

        // Weight loads (L1/L2-hot, independent of row loads).
        const float4 b0 = __ldg(wp + lane);
        const float4 b1 = __ldg(wp + lane + 32);
        float4 bt = make_float4(0.f, 0.f, 0.f, 0.f);
        if (lane < 16) bt = __ldg(wp + 64 + (lane & 3));

        // ---- FMA reduction ----
        float s0 = 0.f, s1 = 0.f, s2 = 0.f, s3 = 0.f;
        s0 = fmaf(a00.x, b0.x, s0); s0 = fmaf(a00.y, b0.y, s0);
        s0 = fmaf(a00.z, b0.z, s0); s0 = fmaf(a00.w, b0.w, s0);
        s0 = fmaf(a01.x, b1.x, s0); s0 = fmaf(a01.y, b1.y, s0);
        s0 = fmaf(a01.z, b1.z, s0); s0 = fmaf(a01.w, b1.w, s0);

        s1 = fmaf(a10.x, b0.x, s1); s1 = fmaf(a10.y, b0.y, s1);
        s1 = fmaf(a10.z, b0.z, s1); s1 = fmaf(a10.w, b0.w, s1);
        s1 = fmaf(a11.x, b1.x, s1); s1 = fmaf(a11.y, b1.y, s1);
        s1 = fmaf(a11.z, b1.z, s1); s1 = fmaf(a11.w, b1.w, s1);

        s2 = fmaf(a20.x, b0.x, s2); s2 = fmaf(a20.y, b0.y, s2);
        s2 = fmaf(a20.z, b0.z, s2); s2 = fmaf(a20.w, b0.w, s2);
        s2 = fmaf(a21.x, b1.x, s2); s2 = fmaf(a21.y, b1.y, s2);
        s2 = fmaf(a21.z, b1.z, s2); s2 = fmaf(a21.w, b1.w, s2);

        s3 = fmaf(a30.x, b0.x, s3); s3 = fmaf(a30.y, b0.y, s3);
        s3 = fmaf(a30.z, b0.z, s3); s3 = fmaf(a30.w, b0.w, s3);
        s3 = fmaf(a31.x, b1.x, s3); s3 = fmaf(a31.y, b1.y, s3);
        s3 = fmaf(a31.z, b1.z, s3); s3 = fmaf(a31.w, b1.w, s3);

        // Tail: lane/4 selects destination accumulator.
        const float ts = fmaf(at.x, bt.x,
                         fmaf(at.y, bt.y,
                         fmaf(at.z, bt.z, at.w * bt.w)));
        const int tr = lane >> 2;
        if (lane < 16) {
            if      (tr == 0) s0 += ts;
            else if (tr == 1) s1 += ts;
            else if (tr == 2) s2 += ts;
            else              s3 += ts;
        }

        // ---- Merged butterfly reduce: 9 shuffles total ----
        float x01 = (lane & 1) ? s1 : s0;
        float y01 = (lane & 1) ? s0 : s1;
        x01 += __shfl_xor_sync(0xFFFFFFFFu, y01, 1);
        float x23 = (lane & 1) ? s3 : s2;
        float y23 = (lane & 1) ? s2 : s3;
        x23 += __shfl_xor_sync(0xFFFFFFFFu, y23, 1);
        float x = (lane & 2) ? x23 : x01;
        float y = (lane & 2) ? x01 : x23;
        x += __shfl_xor_sync(0xFFFFFFFFu, y, 2);
        x += __shfl_xor_sync(0xFFFFFFFFu, x, 4);
        x += __shfl_xor_sync(0xFFFFFFFFu, x, 8);
        x += __shfl_xor_sync(0xFFFFFFFFu, x, 16);

        // Lane j (j<4) holds total for row0+j. 16B coalesced store.
        if (lane < 4) out[row0 + lane] = x + g_bias;
    } else {
        // Remainder rows (n not multiple of 4): one row at a time, warp-wide.
        const float4 b0 = __ldg(wp + lane);
        const float4 b1 = __ldg(wp + lane + 32);
        for (long long r = row0; r < n; ++r) {
            const float4* rp = in4 + r * D4;
            float s = 0.f;
            float4 a = ldcs4(rp + lane);
            s = fmaf(a.x, b0.x, s); s = fmaf(a.y, b0.y, s);
            s = fmaf(a.z, b0.z, s); s = fmaf(a.w, b0.w, s);
            a = ldcs4(rp + lane + 32);
            s = fmaf(a.x, b1.x, s); s = fmaf(a.y, b1.y, s);
            s = fmaf(a.z, b1.z, s); s = fmaf(a.w, b1.w, s);
            if (lane < 4) {
                float4 t = ldcs4(rp + 64 + lane);
                float4 bw = __ldg(wp + 64 + lane);
                s = fmaf(t.x, bw.x, s); s = fmaf(t.y, bw.y, s);
                s = fmaf(t.z, bw.z, s); s = fmaf(t.w, bw.w, s);
            }
            #pragma unroll
            for (int off = 16; off > 0; off >>= 1)
                s += __shfl_xor_sync(0xFFFFFFFFu, s, off);
            if (lane == 0) out[r] = s + g_bias;
        }
    }
}

extern "C" void kernel_launch(void* const* d_in, const int* in_sizes, int n_in,
                              void* d_out, int out_size)
{
    const float* in   = (const float*)d_in[0];   // [N, 272]
    const float* kern = (const float*)d_in[1];   // [16]
    const float* w1   = (const float*)d_in[2];   // [1]
    const float* w2   = (const float*)d_in[3];   // [1]
    const float* bias = (const float*)d_in[4];   // [1]
    float* out = (float*)d_out;

    const int n = out_size;  // 500000 rows
    const int blocks = (n + ROWS_PER_BLOCK - 1) / ROWS_PER_BLOCK;

    build_weights_kernel<<<1, 256>>>(kern, w1, w2, bias);
    linear_gemv_kernel<<<blocks, THREADS>>>(in, out, n);
}